// round 16
// baseline (speedup 1.0000x reference)
#include <cuda_runtime.h>
#include <cuda_bf16.h>
#include <cuda_fp16.h>
#include <cstdint>

#define N_NODES 100000
#define N_EDGES 3200000
#define D_IN 256
#define D_OUT 256

#define SCAN_CHUNK 1024
#define N_CHUNKS ((N_NODES + SCAN_CHUNK - 1) / SCAN_CHUNK)   // 98

// ---------------------------------------------------------------------------
// Scratch (allocation-free device globals)
// ---------------------------------------------------------------------------
__device__ __half g_support_h[(size_t)N_NODES * D_OUT];  // X @ W, fp16 (51 MB)
__device__ __half g_Wt[D_OUT * D_IN];                    // W^T fp16 [n][k]
__device__ int   g_count[N_NODES];
__device__ int   g_offsets[N_NODES];
__device__ int   g_chunk_sums[N_CHUNKS];
__device__ int2  g_perm[N_EDGES];

// ---------------------------------------------------------------------------
// Side stream + events (created once at load; no device allocation)
// ---------------------------------------------------------------------------
namespace {
struct SideRes {
    cudaStream_t s;
    cudaEvent_t fork_ev, join_ev;
    SideRes() {
        cudaStreamCreateWithFlags(&s, cudaStreamNonBlocking);
        cudaEventCreateWithFlags(&fork_ev, cudaEventDisableTiming);
        cudaEventCreateWithFlags(&join_ev, cudaEventDisableTiming);
    }
};
SideRes g_side;
}

// ---------------------------------------------------------------------------
// helpers
// ---------------------------------------------------------------------------
__device__ __forceinline__ uint32_t smem_to_u32(const void* p) {
    uint32_t a;
    asm("{ .reg .u64 t; cvta.to.shared.u64 t, %1; cvt.u32.u64 %0, t; }" : "=r"(a) : "l"(p));
    return a;
}
__device__ __forceinline__ void ldsm_x4(uint32_t r[4], uint32_t addr) {
    asm volatile("ldmatrix.sync.aligned.m8n8.x4.shared.b16 {%0,%1,%2,%3}, [%4];"
                 : "=r"(r[0]), "=r"(r[1]), "=r"(r[2]), "=r"(r[3]) : "r"(addr));
}
__device__ __forceinline__ void mma_fp16(float c[4], const uint32_t a[4],
                                         uint32_t b0, uint32_t b1) {
    asm volatile(
        "mma.sync.aligned.m16n8k16.row.col.f32.f16.f16.f32 "
        "{%0,%1,%2,%3}, {%4,%5,%6,%7}, {%8,%9}, {%0,%1,%2,%3};"
        : "+f"(c[0]), "+f"(c[1]), "+f"(c[2]), "+f"(c[3])
        : "r"(a[0]), "r"(a[1]), "r"(a[2]), "r"(a[3]), "r"(b0), "r"(b1));
}
__device__ __forceinline__ void cp_async16(uint32_t smem_dst, const void* gsrc) {
    asm volatile("cp.async.cg.shared.global [%0], [%1], 16;"
                 :: "r"(smem_dst), "l"(__cvta_generic_to_global(gsrc)));
}
#define CP_COMMIT() asm volatile("cp.async.commit_group;")
#define CP_WAIT0()  asm volatile("cp.async.wait_group 0;")

__device__ __forceinline__ uint32_t pack_fp16(float x, float y) {
    __half2 h = __floats2half2_rn(x, y);
    return *(uint32_t*)&h;
}

// Gather load: no L1 allocation (rows reused only via L2)
__device__ __forceinline__ uint4 ldg_nc_noalloc(const void* p) {
    uint4 v;
    asm volatile("ld.global.nc.L1::no_allocate.v4.u32 {%0,%1,%2,%3}, [%4];"
                 : "=r"(v.x), "=r"(v.y), "=r"(v.z), "=r"(v.w)
                 : "l"(__cvta_generic_to_global(p)));
    return v;
}

// ---------------------------------------------------------------------------
// Kernel 0: W transpose + fp16 convert   Wt[n][k] = fp16(W[k][n])
// ---------------------------------------------------------------------------
__global__ __launch_bounds__(256) void wsplit_kernel(const float* __restrict__ W)
{
    const int k = blockIdx.x;
    const int n = threadIdx.x;
    g_Wt[n * D_IN + k] = __float2half_rn(W[k * D_OUT + n]);
}

// ---------------------------------------------------------------------------
// Kernel 1: mma.sync fp16 GEMM   support_h = fp16(X @ W)   [R13 champion]
// CTA tile: M=64, N=256, K chunks of 64.  8 warps = 2(m) x 4(n); warp 32x64.
// (256,2); smem rows 128 B data padded to 144 B (conflict-free ldmatrix).
// ---------------------------------------------------------------------------
#define GBK 64
#define N_GCHUNK (D_IN / GBK)          // 4
#define ROWB 144
#define SA_OFF 0
#define SB_OFF (64 * ROWB)             // 9216
#define STAGE_BYTES (SB_OFF + 256 * ROWB)   // 46080
#define GEMM_SMEM (2 * STAGE_BYTES)    // 92160

__global__ __launch_bounds__(256, 2) void gemm_mma_kernel(const float* __restrict__ X,
                                                          __half* __restrict__ C)
{
    extern __shared__ char smem[];
    const uint32_t sbase = smem_to_u32(smem);
    const int tid  = threadIdx.x;
    const int lane = tid & 31;
    const int wid  = tid >> 5;
    const int wm   = wid >> 2;         // 0..1
    const int wn   = wid & 3;          // 0..3
    const int tileBase = blockIdx.x * 64;

    const int a_row = tid >> 2;            // 0..63
    const int a_q   = tid & 3;             // 32B quarter

    float4 apf0, apf1, apf2, apf3;
    float acc[2][8][4];
    #pragma unroll
    for (int i = 0; i < 2; i++)
        #pragma unroll
        for (int j = 0; j < 8; j++)
            #pragma unroll
            for (int q = 0; q < 4; q++) acc[i][j][q] = 0.f;

    #define LOAD_A(ch) do {                                                   \
        const int gr = tileBase + a_row;                                      \
        if (gr < N_NODES) {                                                   \
            const float* s = X + (size_t)gr * D_IN + (ch) * GBK + a_q * 16;   \
            apf0 = *(const float4*)s;                                         \
            apf1 = *(const float4*)(s + 4);                                   \
            apf2 = *(const float4*)(s + 8);                                   \
            apf3 = *(const float4*)(s + 12);                                  \
        } else {                                                              \
            apf0 = make_float4(0.f,0.f,0.f,0.f);                              \
            apf1 = apf0; apf2 = apf0; apf3 = apf0;                            \
        } } while (0)

    #define STS_A(st) do {                                                    \
        char* base = smem + (st) * STAGE_BYTES;                               \
        uint32_t off = (uint32_t)(a_row * ROWB + a_q * 32);                   \
        uint4 h0 = make_uint4(pack_fp16(apf0.x, apf0.y),                      \
                              pack_fp16(apf0.z, apf0.w),                      \
                              pack_fp16(apf1.x, apf1.y),                      \
                              pack_fp16(apf1.z, apf1.w));                     \
        uint4 h1 = make_uint4(pack_fp16(apf2.x, apf2.y),                      \
                              pack_fp16(apf2.z, apf2.w),                      \
                              pack_fp16(apf3.x, apf3.y),                      \
                              pack_fp16(apf3.z, apf3.w));                     \
        *(uint4*)(base + SA_OFF + off)      = h0;                             \
        *(uint4*)(base + SA_OFF + off + 16) = h1;                             \
    } while (0)

    #define CP_B(ch, st) do {                                                 \
        const uint32_t stb = sbase + (st) * STAGE_BYTES;                      \
        _Pragma("unroll")                                                     \
        for (int i = 0; i < 8; i++) {                                         \
            const int idx = i * 256 + tid;                                    \
            const int n = idx >> 3, c = idx & 7;                              \
            const char* sh = (const char*)g_Wt + (size_t)n * 512 + (ch) * 128 + c * 16; \
            const uint32_t so = (uint32_t)(n * ROWB + c * 16);                \
            cp_async16(stb + SB_OFF + so, sh);                                \
        } } while (0)

    LOAD_A(0);
    CP_B(0, 0);
    CP_COMMIT();
    STS_A(0);
    CP_WAIT0();
    __syncthreads();

    for (int ch = 0; ch < N_GCHUNK; ch++) {
        const int st = ch & 1;
        if (ch + 1 < N_GCHUNK) {
            LOAD_A(ch + 1);
            CP_B(ch + 1, st ^ 1);
            CP_COMMIT();
        }

        {
            const uint32_t sa = sbase + st * STAGE_BYTES + SA_OFF;
            const uint32_t sb = sbase + st * STAGE_BYTES + SB_OFF;
            const int arow_off = (lane & 15);
            const int akblk    = (lane >> 4) * 8;
            const int bn_off   = ((lane >> 4) << 3) + (lane & 7);
            const int bkblk    = ((lane >> 3) & 1) << 3;

            #pragma unroll
            for (int kk = 0; kk < 4; kk++) {
                uint32_t ah[2][4];
                #pragma unroll
                for (int mi = 0; mi < 2; mi++) {
                    const uint32_t ro = (uint32_t)((wm * 32 + mi * 16 + arow_off) * ROWB
                                                   + (kk * 16 + akblk) * 2);
                    ldsm_x4(ah[mi], sa + ro);
                }
                #pragma unroll
                for (int ntp = 0; ntp < 4; ntp++) {
                    const uint32_t bo = (uint32_t)((wn * 64 + ntp * 16 + bn_off) * ROWB
                                                   + (kk * 16 + bkblk) * 2);
                    uint32_t bh[4];
                    ldsm_x4(bh, sb + bo);
                    #pragma unroll
                    for (int mi = 0; mi < 2; mi++) {
                        #pragma unroll
                        for (int s = 0; s < 2; s++) {
                            float* c = acc[mi][ntp * 2 + s];
                            mma_fp16(c, ah[mi], bh[2*s], bh[2*s+1]);
                        }
                    }
                }
            }
        }

        if (ch + 1 < N_GCHUNK) STS_A(st ^ 1);
        CP_WAIT0();
        __syncthreads();
    }

    // ---- epilogue: fp32 acc -> fp16 stores (half2) ----
    #pragma unroll
    for (int mi = 0; mi < 2; mi++) {
        #pragma unroll
        for (int nt = 0; nt < 8; nt++) {
            const int row0 = tileBase + wm * 32 + mi * 16 + (lane >> 2);
            const int col  = wn * 64 + nt * 8 + 2 * (lane & 3);
            if (row0 < N_NODES) {
                __half2 h01 = __floats2half2_rn(acc[mi][nt][0], acc[mi][nt][1]);
                *(__half2*)(C + (size_t)row0 * D_OUT + col) = h01;
            }
            if (row0 + 8 < N_NODES) {
                __half2 h23 = __floats2half2_rn(acc[mi][nt][2], acc[mi][nt][3]);
                *(__half2*)(C + (size_t)(row0 + 8) * D_OUT + col) = h23;
            }
        }
    }
    #undef LOAD_A
    #undef STS_A
    #undef CP_B
}

// ---------------------------------------------------------------------------
// CSR construction: histogram -> scan -> permute
// ---------------------------------------------------------------------------
__global__ __launch_bounds__(256) void histogram_kernel(const int* __restrict__ edge_dst)
{
    int e = blockIdx.x * blockDim.x + threadIdx.x;
    if (e < N_EDGES)
        atomicAdd(&g_count[edge_dst[e]], 1);
}

__global__ __launch_bounds__(SCAN_CHUNK) void scan_chunk_kernel()
{
    __shared__ int s[SCAN_CHUNK];
    const int tid = threadIdx.x;
    const int gid = blockIdx.x * SCAN_CHUNK + tid;
    int v = (gid < N_NODES) ? g_count[gid] : 0;
    s[tid] = v;
    __syncthreads();
    #pragma unroll
    for (int d = 1; d < SCAN_CHUNK; d <<= 1) {
        int t = (tid >= d) ? s[tid - d] : 0;
        __syncthreads();
        s[tid] += t;
        __syncthreads();
    }
    int incl = s[tid];
    if (gid < N_NODES)
        g_offsets[gid] = incl - v;
    if (tid == SCAN_CHUNK - 1)
        g_chunk_sums[blockIdx.x] = incl;
}

__global__ void scan_sums_kernel()
{
    __shared__ int s[N_CHUNKS];
    const int tid = threadIdx.x;
    if (tid < N_CHUNKS) s[tid] = g_chunk_sums[tid];
    __syncthreads();
    if (tid == 0) {
        int acc = 0;
        for (int i = 0; i < N_CHUNKS; i++) { int t = s[i]; s[i] = acc; acc += t; }
    }
    __syncthreads();
    if (tid < N_CHUNKS) g_chunk_sums[tid] = s[tid];
}

__global__ __launch_bounds__(SCAN_CHUNK) void scan_apply_kernel()
{
    const int gid = blockIdx.x * SCAN_CHUNK + threadIdx.x;
    if (gid < N_NODES) {
        int off = g_offsets[gid] + g_chunk_sums[blockIdx.x];
        g_offsets[gid] = off;
        g_count[gid] = off;
    }
}

__global__ __launch_bounds__(256) void permute_kernel(
    const int* __restrict__ edge_src,
    const int* __restrict__ edge_dst,
    const float* __restrict__ edge_val)
{
    int e = blockIdx.x * blockDim.x + threadIdx.x;
    if (e >= N_EDGES) return;
    const int dst = edge_dst[e];
    const int pos = atomicAdd(&g_count[dst], 1);
    g_perm[pos] = make_int2(edge_src[e], __float_as_int(edge_val[e]));
}

// ---------------------------------------------------------------------------
// Aggregation: one warp per destination node; no atomics (proven form).
// fp16 gather via ld.global.nc.L1::no_allocate (L2-only reuse), fp32 accum.
// ---------------------------------------------------------------------------
__global__ __launch_bounds__(256) void aggregate_kernel(
    const float* __restrict__ bias,
    float* __restrict__ out)
{
    const int node = (blockIdx.x * blockDim.x + threadIdx.x) >> 5;
    if (node >= N_NODES) return;
    const int lane = threadIdx.x & 31;

    const int beg = g_offsets[node];
    const int end = (node == N_NODES - 1) ? N_EDGES : g_offsets[node + 1];

    float acc[8] = {0.f, 0.f, 0.f, 0.f, 0.f, 0.f, 0.f, 0.f};

    if (beg < end) {
        int2 p = g_perm[beg];
        for (int e = beg; e < end; e++) {
            int2 pn = (e + 1 < end) ? g_perm[e + 1] : make_int2(0, 0);
            const float val = __int_as_float(p.y);
            uint4 v = ldg_nc_noalloc(g_support_h + (size_t)p.x * D_OUT + lane * 8);
            float2 f0 = __half22float2(*(__half2*)&v.x);
            float2 f1 = __half22float2(*(((__half2*)&v.x) + 1));
            float2 f2 = __half22float2(*(__half2*)&v.z);
            float2 f3 = __half22float2(*(((__half2*)&v.z) + 1));
            acc[0] = fmaf(f0.x, val, acc[0]);
            acc[1] = fmaf(f0.y, val, acc[1]);
            acc[2] = fmaf(f1.x, val, acc[2]);
            acc[3] = fmaf(f1.y, val, acc[3]);
            acc[4] = fmaf(f2.x, val, acc[4]);
            acc[5] = fmaf(f2.y, val, acc[5]);
            acc[6] = fmaf(f3.x, val, acc[6]);
            acc[7] = fmaf(f3.y, val, acc[7]);
            p = pn;
        }
    }

    const float4 b0 = *(const float4*)(bias + lane * 8);
    const float4 b1 = *(const float4*)(bias + lane * 8 + 4);
    float4 o0 = make_float4(acc[0] + b0.x, acc[1] + b0.y, acc[2] + b0.z, acc[3] + b0.w);
    float4 o1 = make_float4(acc[4] + b1.x, acc[5] + b1.y, acc[6] + b1.z, acc[7] + b1.w);

    float* __restrict__ orow = out + (size_t)node * D_OUT + lane * 8;
    *(float4*)orow       = o0;
    *(float4*)(orow + 4) = o1;
}

// ---------------------------------------------------------------------------
// Launch: GEMM on main stream, CSR build on side stream, join before aggregate
// ---------------------------------------------------------------------------
extern "C" void kernel_launch(void* const* d_in, const int* in_sizes, int n_in,
                              void* d_out, int out_size)
{
    const float* X        = (const float*)d_in[0];
    const int*   edge_src = (const int*)d_in[1];
    const int*   edge_dst = (const int*)d_in[2];
    const float* edge_val = (const float*)d_in[3];
    const float* W        = (const float*)d_in[4];
    const float* b        = (const float*)d_in[5];
    float* out = (float*)d_out;

    __half* support_h;
    cudaGetSymbolAddress((void**)&support_h, g_support_h);
    int* count_ptr;
    cudaGetSymbolAddress((void**)&count_ptr, g_count);

    cudaStream_t side = g_side.s;

    cudaEventRecord(g_side.fork_ev, 0);
    cudaStreamWaitEvent(side, g_side.fork_ev, 0);

    // ---- main stream: W convert + GEMM ----
    wsplit_kernel<<<D_IN, D_OUT>>>(W);
    cudaFuncSetAttribute(gemm_mma_kernel,
                         cudaFuncAttributeMaxDynamicSharedMemorySize, GEMM_SMEM);
    {
        const int grid = (N_NODES + 63) / 64;   // 1563
        gemm_mma_kernel<<<grid, 256, GEMM_SMEM>>>(X, support_h);
    }

    // ---- side stream: CSR build ----
    cudaMemsetAsync(count_ptr, 0, N_NODES * sizeof(int), side);
    {
        const int blocks = (N_EDGES + 255) / 256;
        histogram_kernel<<<blocks, 256, 0, side>>>(edge_dst);
    }
    scan_chunk_kernel<<<N_CHUNKS, SCAN_CHUNK, 0, side>>>();
    scan_sums_kernel<<<1, 128, 0, side>>>();
    scan_apply_kernel<<<N_CHUNKS, SCAN_CHUNK, 0, side>>>();
    {
        const int blocks = (N_EDGES + 255) / 256;
        permute_kernel<<<blocks, 256, 0, side>>>(edge_src, edge_dst, edge_val);
    }

    cudaEventRecord(g_side.join_ev, side);
    cudaStreamWaitEvent(0, g_side.join_ev, 0);

    // ---- main stream: aggregate ----
    {
        const long long total_threads = (long long)N_NODES * 32;
        const int blocks = (int)((total_threads + 255) / 256);
        aggregate_kernel<<<blocks, 256>>>(b, out);
    }
}

// round 17
// speedup vs baseline: 1.5036x; 1.5036x over previous
#include <cuda_runtime.h>
#include <cuda_bf16.h>
#include <cuda_fp16.h>
#include <cstdint>

#define N_NODES 100000
#define N_EDGES 3200000
#define D_IN 256
#define D_OUT 256

#define SCAN_CHUNK 1024
#define N_CHUNKS ((N_NODES + SCAN_CHUNK - 1) / SCAN_CHUNK)   // 98

// ---------------------------------------------------------------------------
// Scratch (allocation-free device globals)
// ---------------------------------------------------------------------------
__device__ __half g_support_h[(size_t)N_NODES * D_OUT];  // X @ W, fp16 (51 MB)
__device__ __half g_Wt[D_OUT * D_IN];                    // W^T fp16 [n][k]
__device__ int   g_count[N_NODES];
__device__ int   g_offsets[N_NODES];
__device__ int   g_chunk_sums[N_CHUNKS];
__device__ int2  g_perm[N_EDGES];

// ---------------------------------------------------------------------------
// Side stream + events (created once at load; no device allocation)
// ---------------------------------------------------------------------------
namespace {
struct SideRes {
    cudaStream_t s;
    cudaEvent_t fork_ev, join_ev;
    SideRes() {
        cudaStreamCreateWithFlags(&s, cudaStreamNonBlocking);
        cudaEventCreateWithFlags(&fork_ev, cudaEventDisableTiming);
        cudaEventCreateWithFlags(&join_ev, cudaEventDisableTiming);
    }
};
SideRes g_side;
}

// ---------------------------------------------------------------------------
// helpers
// ---------------------------------------------------------------------------
__device__ __forceinline__ uint32_t smem_to_u32(const void* p) {
    uint32_t a;
    asm("{ .reg .u64 t; cvta.to.shared.u64 t, %1; cvt.u32.u64 %0, t; }" : "=r"(a) : "l"(p));
    return a;
}
__device__ __forceinline__ void ldsm_x4(uint32_t r[4], uint32_t addr) {
    asm volatile("ldmatrix.sync.aligned.m8n8.x4.shared.b16 {%0,%1,%2,%3}, [%4];"
                 : "=r"(r[0]), "=r"(r[1]), "=r"(r[2]), "=r"(r[3]) : "r"(addr));
}
__device__ __forceinline__ void mma_fp16(float c[4], const uint32_t a[4],
                                         uint32_t b0, uint32_t b1) {
    asm volatile(
        "mma.sync.aligned.m16n8k16.row.col.f32.f16.f16.f32 "
        "{%0,%1,%2,%3}, {%4,%5,%6,%7}, {%8,%9}, {%0,%1,%2,%3};"
        : "+f"(c[0]), "+f"(c[1]), "+f"(c[2]), "+f"(c[3])
        : "r"(a[0]), "r"(a[1]), "r"(a[2]), "r"(a[3]), "r"(b0), "r"(b1));
}
__device__ __forceinline__ void cp_async16(uint32_t smem_dst, const void* gsrc) {
    asm volatile("cp.async.cg.shared.global [%0], [%1], 16;"
                 :: "r"(smem_dst), "l"(__cvta_generic_to_global(gsrc)));
}
#define CP_COMMIT() asm volatile("cp.async.commit_group;")
#define CP_WAIT0()  asm volatile("cp.async.wait_group 0;")

__device__ __forceinline__ uint32_t pack_fp16(float x, float y) {
    __half2 h = __floats2half2_rn(x, y);
    return *(uint32_t*)&h;
}

// ---------------------------------------------------------------------------
// Kernel 0: W transpose + fp16 convert   Wt[n][k] = fp16(W[k][n])
// ---------------------------------------------------------------------------
__global__ __launch_bounds__(256) void wsplit_kernel(const float* __restrict__ W)
{
    const int k = blockIdx.x;
    const int n = threadIdx.x;
    g_Wt[n * D_IN + k] = __float2half_rn(W[k * D_OUT + n]);
}

// ---------------------------------------------------------------------------
// Kernel 1: mma.sync fp16 GEMM   support_h = fp16(X @ W)   [R13 champion]
// CTA tile: M=64, N=256, K chunks of 64.  8 warps = 2(m) x 4(n); warp 32x64.
// (256,2); smem rows 128 B data padded to 144 B (conflict-free ldmatrix).
// ---------------------------------------------------------------------------
#define GBK 64
#define N_GCHUNK (D_IN / GBK)          // 4
#define ROWB 144
#define SA_OFF 0
#define SB_OFF (64 * ROWB)             // 9216
#define STAGE_BYTES (SB_OFF + 256 * ROWB)   // 46080
#define GEMM_SMEM (2 * STAGE_BYTES)    // 92160

__global__ __launch_bounds__(256, 2) void gemm_mma_kernel(const float* __restrict__ X,
                                                          __half* __restrict__ C)
{
    extern __shared__ char smem[];
    const uint32_t sbase = smem_to_u32(smem);
    const int tid  = threadIdx.x;
    const int lane = tid & 31;
    const int wid  = tid >> 5;
    const int wm   = wid >> 2;         // 0..1
    const int wn   = wid & 3;          // 0..3
    const int tileBase = blockIdx.x * 64;

    const int a_row = tid >> 2;            // 0..63
    const int a_q   = tid & 3;             // 32B quarter

    float4 apf0, apf1, apf2, apf3;
    float acc[2][8][4];
    #pragma unroll
    for (int i = 0; i < 2; i++)
        #pragma unroll
        for (int j = 0; j < 8; j++)
            #pragma unroll
            for (int q = 0; q < 4; q++) acc[i][j][q] = 0.f;

    #define LOAD_A(ch) do {                                                   \
        const int gr = tileBase + a_row;                                      \
        if (gr < N_NODES) {                                                   \
            const float* s = X + (size_t)gr * D_IN + (ch) * GBK + a_q * 16;   \
            apf0 = *(const float4*)s;                                         \
            apf1 = *(const float4*)(s + 4);                                   \
            apf2 = *(const float4*)(s + 8);                                   \
            apf3 = *(const float4*)(s + 12);                                  \
        } else {                                                              \
            apf0 = make_float4(0.f,0.f,0.f,0.f);                              \
            apf1 = apf0; apf2 = apf0; apf3 = apf0;                            \
        } } while (0)

    #define STS_A(st) do {                                                    \
        char* base = smem + (st) * STAGE_BYTES;                               \
        uint32_t off = (uint32_t)(a_row * ROWB + a_q * 32);                   \
        uint4 h0 = make_uint4(pack_fp16(apf0.x, apf0.y),                      \
                              pack_fp16(apf0.z, apf0.w),                      \
                              pack_fp16(apf1.x, apf1.y),                      \
                              pack_fp16(apf1.z, apf1.w));                     \
        uint4 h1 = make_uint4(pack_fp16(apf2.x, apf2.y),                      \
                              pack_fp16(apf2.z, apf2.w),                      \
                              pack_fp16(apf3.x, apf3.y),                      \
                              pack_fp16(apf3.z, apf3.w));                     \
        *(uint4*)(base + SA_OFF + off)      = h0;                             \
        *(uint4*)(base + SA_OFF + off + 16) = h1;                             \
    } while (0)

    #define CP_B(ch, st) do {                                                 \
        const uint32_t stb = sbase + (st) * STAGE_BYTES;                      \
        _Pragma("unroll")                                                     \
        for (int i = 0; i < 8; i++) {                                         \
            const int idx = i * 256 + tid;                                    \
            const int n = idx >> 3, c = idx & 7;                              \
            const char* sh = (const char*)g_Wt + (size_t)n * 512 + (ch) * 128 + c * 16; \
            const uint32_t so = (uint32_t)(n * ROWB + c * 16);                \
            cp_async16(stb + SB_OFF + so, sh);                                \
        } } while (0)

    LOAD_A(0);
    CP_B(0, 0);
    CP_COMMIT();
    STS_A(0);
    CP_WAIT0();
    __syncthreads();

    for (int ch = 0; ch < N_GCHUNK; ch++) {
        const int st = ch & 1;
        if (ch + 1 < N_GCHUNK) {
            LOAD_A(ch + 1);
            CP_B(ch + 1, st ^ 1);
            CP_COMMIT();
        }

        {
            const uint32_t sa = sbase + st * STAGE_BYTES + SA_OFF;
            const uint32_t sb = sbase + st * STAGE_BYTES + SB_OFF;
            const int arow_off = (lane & 15);
            const int akblk    = (lane >> 4) * 8;
            const int bn_off   = ((lane >> 4) << 3) + (lane & 7);
            const int bkblk    = ((lane >> 3) & 1) << 3;

            #pragma unroll
            for (int kk = 0; kk < 4; kk++) {
                uint32_t ah[2][4];
                #pragma unroll
                for (int mi = 0; mi < 2; mi++) {
                    const uint32_t ro = (uint32_t)((wm * 32 + mi * 16 + arow_off) * ROWB
                                                   + (kk * 16 + akblk) * 2);
                    ldsm_x4(ah[mi], sa + ro);
                }
                #pragma unroll
                for (int ntp = 0; ntp < 4; ntp++) {
                    const uint32_t bo = (uint32_t)((wn * 64 + ntp * 16 + bn_off) * ROWB
                                                   + (kk * 16 + bkblk) * 2);
                    uint32_t bh[4];
                    ldsm_x4(bh, sb + bo);
                    #pragma unroll
                    for (int mi = 0; mi < 2; mi++) {
                        #pragma unroll
                        for (int s = 0; s < 2; s++) {
                            float* c = acc[mi][ntp * 2 + s];
                            mma_fp16(c, ah[mi], bh[2*s], bh[2*s+1]);
                        }
                    }
                }
            }
        }

        if (ch + 1 < N_GCHUNK) STS_A(st ^ 1);
        CP_WAIT0();
        __syncthreads();
    }

    // ---- epilogue: fp32 acc -> fp16 stores (half2) ----
    #pragma unroll
    for (int mi = 0; mi < 2; mi++) {
        #pragma unroll
        for (int nt = 0; nt < 8; nt++) {
            const int row0 = tileBase + wm * 32 + mi * 16 + (lane >> 2);
            const int col  = wn * 64 + nt * 8 + 2 * (lane & 3);
            if (row0 < N_NODES) {
                __half2 h01 = __floats2half2_rn(acc[mi][nt][0], acc[mi][nt][1]);
                *(__half2*)(C + (size_t)row0 * D_OUT + col) = h01;
            }
            if (row0 + 8 < N_NODES) {
                __half2 h23 = __floats2half2_rn(acc[mi][nt][2], acc[mi][nt][3]);
                *(__half2*)(C + (size_t)(row0 + 8) * D_OUT + col) = h23;
            }
        }
    }
    #undef LOAD_A
    #undef STS_A
    #undef CP_B
}

// ---------------------------------------------------------------------------
// CSR construction: histogram -> scan -> permute
// ---------------------------------------------------------------------------
__global__ __launch_bounds__(256) void histogram_kernel(const int* __restrict__ edge_dst)
{
    int e = blockIdx.x * blockDim.x + threadIdx.x;
    if (e < N_EDGES)
        atomicAdd(&g_count[edge_dst[e]], 1);
}

__global__ __launch_bounds__(SCAN_CHUNK) void scan_chunk_kernel()
{
    __shared__ int s[SCAN_CHUNK];
    const int tid = threadIdx.x;
    const int gid = blockIdx.x * SCAN_CHUNK + tid;
    int v = (gid < N_NODES) ? g_count[gid] : 0;
    s[tid] = v;
    __syncthreads();
    #pragma unroll
    for (int d = 1; d < SCAN_CHUNK; d <<= 1) {
        int t = (tid >= d) ? s[tid - d] : 0;
        __syncthreads();
        s[tid] += t;
        __syncthreads();
    }
    int incl = s[tid];
    if (gid < N_NODES)
        g_offsets[gid] = incl - v;
    if (tid == SCAN_CHUNK - 1)
        g_chunk_sums[blockIdx.x] = incl;
}

__global__ void scan_sums_kernel()
{
    __shared__ int s[N_CHUNKS];
    const int tid = threadIdx.x;
    if (tid < N_CHUNKS) s[tid] = g_chunk_sums[tid];
    __syncthreads();
    if (tid == 0) {
        int acc = 0;
        for (int i = 0; i < N_CHUNKS; i++) { int t = s[i]; s[i] = acc; acc += t; }
    }
    __syncthreads();
    if (tid < N_CHUNKS) g_chunk_sums[tid] = s[tid];
}

__global__ __launch_bounds__(SCAN_CHUNK) void scan_apply_kernel()
{
    const int gid = blockIdx.x * SCAN_CHUNK + threadIdx.x;
    if (gid < N_NODES) {
        int off = g_offsets[gid] + g_chunk_sums[blockIdx.x];
        g_offsets[gid] = off;
        g_count[gid] = off;
    }
}

__global__ __launch_bounds__(256) void permute_kernel(
    const int* __restrict__ edge_src,
    const int* __restrict__ edge_dst,
    const float* __restrict__ edge_val)
{
    int e = blockIdx.x * blockDim.x + threadIdx.x;
    if (e >= N_EDGES) return;
    const int dst = edge_dst[e];
    const int pos = atomicAdd(&g_count[dst], 1);
    g_perm[pos] = make_int2(edge_src[e], __float_as_int(edge_val[e]));
}

// ---------------------------------------------------------------------------
// Aggregation: one warp per destination node; no atomics (champion form).
// fp16 gather (default caching: L1 reuse is load-bearing), fp32 accumulate.
// ---------------------------------------------------------------------------
__global__ __launch_bounds__(256) void aggregate_kernel(
    const float* __restrict__ bias,
    float* __restrict__ out)
{
    const int node = (blockIdx.x * blockDim.x + threadIdx.x) >> 5;
    if (node >= N_NODES) return;
    const int lane = threadIdx.x & 31;

    const int beg = g_offsets[node];
    const int end = (node == N_NODES - 1) ? N_EDGES : g_offsets[node + 1];

    float acc[8] = {0.f, 0.f, 0.f, 0.f, 0.f, 0.f, 0.f, 0.f};

    if (beg < end) {
        int2 p = g_perm[beg];
        for (int e = beg; e < end; e++) {
            int2 pn = (e + 1 < end) ? g_perm[e + 1] : make_int2(0, 0);
            const float val = __int_as_float(p.y);
            const uint4* __restrict__ row =
                (const uint4*)(g_support_h + (size_t)p.x * D_OUT);
            uint4 v = row[lane];
            float2 f0 = __half22float2(*(__half2*)&v.x);
            float2 f1 = __half22float2(*(((__half2*)&v.x) + 1));
            float2 f2 = __half22float2(*(__half2*)&v.z);
            float2 f3 = __half22float2(*(((__half2*)&v.z) + 1));
            acc[0] = fmaf(f0.x, val, acc[0]);
            acc[1] = fmaf(f0.y, val, acc[1]);
            acc[2] = fmaf(f1.x, val, acc[2]);
            acc[3] = fmaf(f1.y, val, acc[3]);
            acc[4] = fmaf(f2.x, val, acc[4]);
            acc[5] = fmaf(f2.y, val, acc[5]);
            acc[6] = fmaf(f3.x, val, acc[6]);
            acc[7] = fmaf(f3.y, val, acc[7]);
            p = pn;
        }
    }

    const float4 b0 = *(const float4*)(bias + lane * 8);
    const float4 b1 = *(const float4*)(bias + lane * 8 + 4);
    float4 o0 = make_float4(acc[0] + b0.x, acc[1] + b0.y, acc[2] + b0.z, acc[3] + b0.w);
    float4 o1 = make_float4(acc[4] + b1.x, acc[5] + b1.y, acc[6] + b1.z, acc[7] + b1.w);

    float* __restrict__ orow = out + (size_t)node * D_OUT + lane * 8;
    *(float4*)orow       = o0;
    *(float4*)(orow + 4) = o1;
}

// ---------------------------------------------------------------------------
// Launch: GEMM on main stream, CSR build on side stream, join before aggregate
// ---------------------------------------------------------------------------
extern "C" void kernel_launch(void* const* d_in, const int* in_sizes, int n_in,
                              void* d_out, int out_size)
{
    const float* X        = (const float*)d_in[0];
    const int*   edge_src = (const int*)d_in[1];
    const int*   edge_dst = (const int*)d_in[2];
    const float* edge_val = (const float*)d_in[3];
    const float* W        = (const float*)d_in[4];
    const float* b        = (const float*)d_in[5];
    float* out = (float*)d_out;

    __half* support_h;
    cudaGetSymbolAddress((void**)&support_h, g_support_h);
    int* count_ptr;
    cudaGetSymbolAddress((void**)&count_ptr, g_count);

    cudaStream_t side = g_side.s;

    cudaEventRecord(g_side.fork_ev, 0);
    cudaStreamWaitEvent(side, g_side.fork_ev, 0);

    // ---- main stream: W convert + GEMM ----
    wsplit_kernel<<<D_IN, D_OUT>>>(W);
    cudaFuncSetAttribute(gemm_mma_kernel,
                         cudaFuncAttributeMaxDynamicSharedMemorySize, GEMM_SMEM);
    {
        const int grid = (N_NODES + 63) / 64;   // 1563
        gemm_mma_kernel<<<grid, 256, GEMM_SMEM>>>(X, support_h);
    }

    // ---- side stream: CSR build ----
    cudaMemsetAsync(count_ptr, 0, N_NODES * sizeof(int), side);
    {
        const int blocks = (N_EDGES + 255) / 256;
        histogram_kernel<<<blocks, 256, 0, side>>>(edge_dst);
    }
    scan_chunk_kernel<<<N_CHUNKS, SCAN_CHUNK, 0, side>>>();
    scan_sums_kernel<<<1, 128, 0, side>>>();
    scan_apply_kernel<<<N_CHUNKS, SCAN_CHUNK, 0, side>>>();
    {
        const int blocks = (N_EDGES + 255) / 256;
        permute_kernel<<<blocks, 256, 0, side>>>(edge_src, edge_dst, edge_val);
    }

    cudaEventRecord(g_side.join_ev, side);
    cudaStreamWaitEvent(0, g_side.join_ev, 0);

    // ---- main stream: aggregate ----
    {
        const long long total_threads = (long long)N_NODES * 32;
        const int blocks = (int)((total_threads + 255) / 256);
        aggregate_kernel<<<blocks, 256>>>(b, out);
    }
}